// round 1
// baseline (speedup 1.0000x reference)
#include <cuda_runtime.h>

// Problem-sized scratch (spec constants; guarded by runtime sizes from in_sizes)
//   g_sum : per-torus-node accumulator {sum_x, sum_y, sum_z, count}
//   g_first: per-terrain-node first assignment edge index (segment_min)
__device__ float4 g_sum[1000000];
__device__ int    g_first[2000000];

#define HX_INT_MAX 0x7fffffff

// ---------------------------------------------------------------------------
// Kernel 1: init. Copy x_terrain -> out terrain region (residual base that the
// seq conv atomically adds into), zero g_sum, set g_first = INT_MAX.
// n_t (=2M) >= n_tor (=1M) and n_t == len(g_first), so one index domain covers all.
// ---------------------------------------------------------------------------
__global__ void k_init(const float4* __restrict__ x_terrain4,
                       float4* __restrict__ out_t4,
                       int n_t, int n_tor) {
    int i = blockIdx.x * blockDim.x + threadIdx.x;
    if (i >= n_t) return;
    out_t4[i] = x_terrain4[i];
    g_first[i] = HX_INT_MAX;
    if (i < n_tor) g_sum[i] = make_float4(0.f, 0.f, 0.f, 0.f);
}

// ---------------------------------------------------------------------------
// Kernel 2: fused sequence-conv message scatter + assignment segment-min.
// Both edge sets have E = 2M edges -> same index domain.
//   msg_i = sum_j W_seq[i][j] * x[src][j]   (y = x @ W.T)
//   red.v4 into out_t[dst]  (out_t already holds x_terrain -> residual add free)
//   atomicMin(g_first[assign_src[e]], e)
// ---------------------------------------------------------------------------
__global__ void k_edges_a(const int* __restrict__ seq_src,
                          const int* __restrict__ seq_dst,
                          const int* __restrict__ assign_src,
                          const float4* __restrict__ x_terrain4,
                          const float* __restrict__ W_seq,
                          float4* __restrict__ out_t4,
                          int e_seq) {
    int e = blockIdx.x * blockDim.x + threadIdx.x;
    if (e >= e_seq) return;

    int s = seq_src[e];
    int d = seq_dst[e];
    float4 x = __ldg(&x_terrain4[s]);

    float w[16];
#pragma unroll
    for (int j = 0; j < 16; ++j) w[j] = __ldg(&W_seq[j]);

    float m0 = w[0]  * x.x + w[1]  * x.y + w[2]  * x.z + w[3]  * x.w;
    float m1 = w[4]  * x.x + w[5]  * x.y + w[6]  * x.z + w[7]  * x.w;
    float m2 = w[8]  * x.x + w[9]  * x.y + w[10] * x.z + w[11] * x.w;
    float m3 = w[12] * x.x + w[13] * x.y + w[14] * x.z + w[15] * x.w;

    float4* dst = &out_t4[d];
    asm volatile("red.global.add.v4.f32 [%0], {%1, %2, %3, %4};"
                 :: "l"(dst), "f"(m0), "f"(m1), "f"(m2), "f"(m3) : "memory");

    atomicMin(&g_first[assign_src[e]], e);
}

// ---------------------------------------------------------------------------
// Kernel 3: per-node operator transform (in-place on out terrain region).
//   f = g_first[n]; if f < E: y = op_W[op] @ [x_t, pol] + op_b[op]
// ---------------------------------------------------------------------------
__global__ void k_op(float4* __restrict__ out_t4,
                     const int* __restrict__ assign_dst,
                     const float* __restrict__ polarity,
                     const float* __restrict__ op_W,
                     const float* __restrict__ op_b,
                     int n_t, int e_as, int n_ops) {
    int n = blockIdx.x * blockDim.x + threadIdx.x;
    if (n >= n_t) return;
    int f = g_first[n];
    if (f >= e_as) return;   // no assignment: keep x_t

    float4 x = out_t4[n];
    int op = __ldg(&assign_dst[f]);
    op = max(0, min(op, n_ops - 1));
    float p = __ldg(&polarity[f]);

    const float* W = op_W + op * 20;   // [4][5] row-major
    const float* b = op_b + op * 4;

    float4 y;
    y.x = __ldg(&W[0])  * x.x + __ldg(&W[1])  * x.y + __ldg(&W[2])  * x.z + __ldg(&W[3])  * x.w + __ldg(&W[4])  * p + __ldg(&b[0]);
    y.y = __ldg(&W[5])  * x.x + __ldg(&W[6])  * x.y + __ldg(&W[7])  * x.z + __ldg(&W[8])  * x.w + __ldg(&W[9])  * p + __ldg(&b[1]);
    y.z = __ldg(&W[10]) * x.x + __ldg(&W[11]) * x.y + __ldg(&W[12]) * x.z + __ldg(&W[13]) * x.w + __ldg(&W[14]) * p + __ldg(&b[2]);
    y.w = __ldg(&W[15]) * x.x + __ldg(&W[16]) * x.y + __ldg(&W[17]) * x.z + __ldg(&W[18]) * x.w + __ldg(&W[19]) * p + __ldg(&b[3]);
    out_t4[n] = y;
}

// ---------------------------------------------------------------------------
// Kernel 4: transport edges. gate = sigmoid([x[dst], x[src]] @ gate_W + gate_b)
// One vector red per edge: {g*xj, 1.0f} accumulated into g_sum[dst].
// ---------------------------------------------------------------------------
__global__ void k_transport(const int* __restrict__ tr_src,
                            const int* __restrict__ tr_dst,
                            const float* __restrict__ x_tor,
                            const float* __restrict__ gate_W,
                            const float* __restrict__ gate_b,
                            int e_tr) {
    int e = blockIdx.x * blockDim.x + threadIdx.x;
    if (e >= e_tr) return;

    int s = tr_src[e];
    int d = tr_dst[e];

    float xi0 = __ldg(&x_tor[3 * d + 0]);
    float xi1 = __ldg(&x_tor[3 * d + 1]);
    float xi2 = __ldg(&x_tor[3 * d + 2]);
    float xj0 = __ldg(&x_tor[3 * s + 0]);
    float xj1 = __ldg(&x_tor[3 * s + 1]);
    float xj2 = __ldg(&x_tor[3 * s + 2]);

    float z = __ldg(&gate_W[0]) * xi0 + __ldg(&gate_W[1]) * xi1 + __ldg(&gate_W[2]) * xi2
            + __ldg(&gate_W[3]) * xj0 + __ldg(&gate_W[4]) * xj1 + __ldg(&gate_W[5]) * xj2
            + __ldg(&gate_b[0]);
    float g = 1.0f / (1.0f + __expf(-z));

    float4* dst = &g_sum[d];
    asm volatile("red.global.add.v4.f32 [%0], {%1, %2, %3, %4};"
                 :: "l"(dst), "f"(g * xj0), "f"(g * xj1), "f"(g * xj2), "f"(1.0f) : "memory");
}

// ---------------------------------------------------------------------------
// Kernel 5: torus finalize. out = x_torus + sum / max(count, 1)
// ---------------------------------------------------------------------------
__global__ void k_finalize(const float* __restrict__ x_tor,
                           float* __restrict__ out_tor,
                           int n_tor) {
    int n = blockIdx.x * blockDim.x + threadIdx.x;
    if (n >= n_tor) return;
    float4 sv = g_sum[n];
    float inv = 1.0f / fmaxf(sv.w, 1.0f);
    out_tor[3 * n + 0] = x_tor[3 * n + 0] + sv.x * inv;
    out_tor[3 * n + 1] = x_tor[3 * n + 1] + sv.y * inv;
    out_tor[3 * n + 2] = x_tor[3 * n + 2] + sv.z * inv;
}

extern "C" void kernel_launch(void* const* d_in, const int* in_sizes, int n_in,
                              void* d_out, int out_size) {
    const float* x_terrain  = (const float*)d_in[0];
    const float* polarity   = (const float*)d_in[1];
    const float* x_torus    = (const float*)d_in[2];
    const int*   seq_ei     = (const int*)d_in[3];
    const int*   assign_src = (const int*)d_in[4];
    const int*   assign_dst = (const int*)d_in[5];
    const int*   tr_ei      = (const int*)d_in[6];
    const float* W_seq      = (const float*)d_in[7];
    const float* op_W       = (const float*)d_in[8];
    const float* op_b       = (const float*)d_in[9];
    const float* gate_W     = (const float*)d_in[10];
    const float* gate_b     = (const float*)d_in[11];

    const int TD = 4, OD = 3;
    int n_t   = in_sizes[0] / TD;      // 2,000,000
    int e_as  = in_sizes[4];           // 2,000,000
    int n_tor = in_sizes[2] / OD;      // 1,000,000
    int e_seq = in_sizes[3] / 2;       // 2,000,000
    int e_tr  = in_sizes[6] / 2;       // 8,000,000
    int n_ops = in_sizes[9] / TD;      // 4

    float* out_t   = (float*)d_out;            // [n_t, 4]
    float* out_tor = out_t + (size_t)n_t * TD; // [n_tor, 3]

    const int B = 256;
    k_init<<<(n_t + B - 1) / B, B>>>((const float4*)x_terrain, (float4*)out_t, n_t, n_tor);

    k_edges_a<<<(e_seq + B - 1) / B, B>>>(seq_ei, seq_ei + e_seq, assign_src,
                                          (const float4*)x_terrain, W_seq,
                                          (float4*)out_t, e_seq);

    k_op<<<(n_t + B - 1) / B, B>>>((float4*)out_t, assign_dst, polarity,
                                   op_W, op_b, n_t, e_as, n_ops);

    k_transport<<<(e_tr + B - 1) / B, B>>>(tr_ei, tr_ei + e_tr, x_torus,
                                           gate_W, gate_b, e_tr);

    k_finalize<<<(n_tor + B - 1) / B, B>>>(x_torus, out_tor, n_tor);
}

// round 2
// speedup vs baseline: 1.0924x; 1.0924x over previous
#include <cuda_runtime.h>

// Scratch (problem-sized per spec):
//   g_sum   : per-torus-node accumulator {sum_x, sum_y, sum_z, count}
//   g_stage : per-torus-node {x, y, z, precomputed_dst_gate_term}
//   g_first : per-terrain-node first assignment edge (segment_min)
__device__ float4 g_sum[1000000];
__device__ float4 g_stage[1000000];
__device__ int    g_first[2000000];

#define HX_INT_MAX 0x7fffffff

// ---------------------------------------------------------------------------
// Kernel 1: init.
//  - copy x_terrain -> out terrain region (residual base for seq scatter-add)
//  - g_first = INT_MAX
//  - g_sum = 0
//  - g_stage[n] = {x_tor[n], a_n} where a_n = gate_W[0:3]·x_tor[n] + gate_b
// ---------------------------------------------------------------------------
__global__ void k_init(const float4* __restrict__ x_terrain4,
                       float4* __restrict__ out_t4,
                       const float* __restrict__ x_tor,
                       const float* __restrict__ gate_W,
                       const float* __restrict__ gate_b,
                       int n_t, int n_tor) {
    int i = blockIdx.x * blockDim.x + threadIdx.x;
    if (i >= n_t) return;
    out_t4[i] = x_terrain4[i];
    g_first[i] = HX_INT_MAX;
    if (i < n_tor) {
        g_sum[i] = make_float4(0.f, 0.f, 0.f, 0.f);
        float x0 = x_tor[3 * i + 0];
        float x1 = x_tor[3 * i + 1];
        float x2 = x_tor[3 * i + 2];
        float a = __ldg(&gate_W[0]) * x0 + __ldg(&gate_W[1]) * x1
                + __ldg(&gate_W[2]) * x2 + __ldg(&gate_b[0]);
        g_stage[i] = make_float4(x0, x1, x2, a);
    }
}

// ---------------------------------------------------------------------------
// Kernel 2: fused sequence-conv scatter + assignment segment-min.
// 2 edges per thread (int2 index loads).
// ---------------------------------------------------------------------------
__global__ void k_edges_a(const int* __restrict__ seq_src,
                          const int* __restrict__ seq_dst,
                          const int* __restrict__ assign_src,
                          const float4* __restrict__ x_terrain4,
                          const float* __restrict__ W_seq,
                          float4* __restrict__ out_t4,
                          int e_seq) {
    int t = blockIdx.x * blockDim.x + threadIdx.x;
    int e0 = 2 * t;
    if (e0 >= e_seq) return;

    float w[16];
#pragma unroll
    for (int j = 0; j < 16; ++j) w[j] = __ldg(&W_seq[j]);

    int n = (e0 + 1 < e_seq) ? 2 : 1;
    int2 s2, d2, a2;
    if (n == 2) {
        s2 = __ldg((const int2*)(seq_src) + t);
        d2 = __ldg((const int2*)(seq_dst) + t);
        a2 = __ldg((const int2*)(assign_src) + t);
    } else {
        s2.x = seq_src[e0]; d2.x = seq_dst[e0]; a2.x = assign_src[e0];
        s2.y = 0; d2.y = 0; a2.y = 0;
    }

#pragma unroll
    for (int k = 0; k < 2; ++k) {
        if (k >= n) break;
        int s = (k == 0) ? s2.x : s2.y;
        int d = (k == 0) ? d2.x : d2.y;
        int a = (k == 0) ? a2.x : a2.y;
        float4 x = __ldg(&x_terrain4[s]);
        float m0 = w[0]  * x.x + w[1]  * x.y + w[2]  * x.z + w[3]  * x.w;
        float m1 = w[4]  * x.x + w[5]  * x.y + w[6]  * x.z + w[7]  * x.w;
        float m2 = w[8]  * x.x + w[9]  * x.y + w[10] * x.z + w[11] * x.w;
        float m3 = w[12] * x.x + w[13] * x.y + w[14] * x.z + w[15] * x.w;
        float4* dst = &out_t4[d];
        asm volatile("red.global.add.v4.f32 [%0], {%1, %2, %3, %4};"
                     :: "l"(dst), "f"(m0), "f"(m1), "f"(m2), "f"(m3) : "memory");
        atomicMin(&g_first[a], e0 + k);
    }
}

// ---------------------------------------------------------------------------
// Kernel 3: per-node operator transform (in-place).
// ---------------------------------------------------------------------------
__global__ void k_op(float4* __restrict__ out_t4,
                     const int* __restrict__ assign_dst,
                     const float* __restrict__ polarity,
                     const float* __restrict__ op_W,
                     const float* __restrict__ op_b,
                     int n_t, int e_as, int n_ops) {
    int n = blockIdx.x * blockDim.x + threadIdx.x;
    if (n >= n_t) return;
    int f = g_first[n];
    if (f >= e_as) return;

    float4 x = out_t4[n];
    int op = __ldg(&assign_dst[f]);
    op = max(0, min(op, n_ops - 1));
    float p = __ldg(&polarity[f]);

    const float* W = op_W + op * 20;   // [4][5] row-major
    const float* b = op_b + op * 4;

    float4 y;
    y.x = __ldg(&W[0])  * x.x + __ldg(&W[1])  * x.y + __ldg(&W[2])  * x.z + __ldg(&W[3])  * x.w + __ldg(&W[4])  * p + __ldg(&b[0]);
    y.y = __ldg(&W[5])  * x.x + __ldg(&W[6])  * x.y + __ldg(&W[7])  * x.z + __ldg(&W[8])  * x.w + __ldg(&W[9])  * p + __ldg(&b[1]);
    y.z = __ldg(&W[10]) * x.x + __ldg(&W[11]) * x.y + __ldg(&W[12]) * x.z + __ldg(&W[13]) * x.w + __ldg(&W[14]) * p + __ldg(&b[2]);
    y.w = __ldg(&W[15]) * x.x + __ldg(&W[16]) * x.y + __ldg(&W[17]) * x.z + __ldg(&W[18]) * x.w + __ldg(&W[19]) * p + __ldg(&b[3]);
    out_t4[n] = y;
}

// ---------------------------------------------------------------------------
// Kernel 4: transport edges, 4 edges per thread (int4 index loads).
// Per edge: 1× LDG.128 (stage[src] = {xj, a_src}), 1× LDG.32 (stage[dst].w = a_dst),
//           1× RED.128 into g_sum[dst].
// gate = sigmoid(a_dst + gate_W[3:6]·xj)
// ---------------------------------------------------------------------------
__global__ void k_transport(const int* __restrict__ tr_src,
                            const int* __restrict__ tr_dst,
                            const float* __restrict__ gate_W,
                            int e_tr) {
    int t = blockIdx.x * blockDim.x + threadIdx.x;
    int e0 = 4 * t;
    if (e0 >= e_tr) return;

    float w3 = __ldg(&gate_W[3]);
    float w4 = __ldg(&gate_W[4]);
    float w5 = __ldg(&gate_W[5]);

    const float* stage_f = (const float*)g_stage;

    if (e0 + 3 < e_tr) {
        int4 s4 = __ldg((const int4*)(tr_src) + t);
        int4 d4 = __ldg((const int4*)(tr_dst) + t);
        int ss[4] = {s4.x, s4.y, s4.z, s4.w};
        int dd[4] = {d4.x, d4.y, d4.z, d4.w};
#pragma unroll
        for (int k = 0; k < 4; ++k) {
            float4 v = __ldg(&g_stage[ss[k]]);
            float a  = __ldg(&stage_f[4 * dd[k] + 3]);
            float z  = a + w3 * v.x + w4 * v.y + w5 * v.z;
            float g  = 1.0f / (1.0f + __expf(-z));
            float4* dst = &g_sum[dd[k]];
            asm volatile("red.global.add.v4.f32 [%0], {%1, %2, %3, %4};"
                         :: "l"(dst), "f"(g * v.x), "f"(g * v.y), "f"(g * v.z), "f"(1.0f)
                         : "memory");
        }
    } else {
        for (int e = e0; e < e_tr; ++e) {
            int s = tr_src[e];
            int d = tr_dst[e];
            float4 v = __ldg(&g_stage[s]);
            float a  = __ldg(&stage_f[4 * d + 3]);
            float z  = a + w3 * v.x + w4 * v.y + w5 * v.z;
            float g  = 1.0f / (1.0f + __expf(-z));
            float4* dst = &g_sum[d];
            asm volatile("red.global.add.v4.f32 [%0], {%1, %2, %3, %4};"
                         :: "l"(dst), "f"(g * v.x), "f"(g * v.y), "f"(g * v.z), "f"(1.0f)
                         : "memory");
        }
    }
}

// ---------------------------------------------------------------------------
// Kernel 5: torus finalize. out = x + sum / max(count, 1)
// ---------------------------------------------------------------------------
__global__ void k_finalize(float* __restrict__ out_tor, int n_tor) {
    int n = blockIdx.x * blockDim.x + threadIdx.x;
    if (n >= n_tor) return;
    float4 sv = g_sum[n];
    float4 xv = g_stage[n];
    float inv = 1.0f / fmaxf(sv.w, 1.0f);
    out_tor[3 * n + 0] = xv.x + sv.x * inv;
    out_tor[3 * n + 1] = xv.y + sv.y * inv;
    out_tor[3 * n + 2] = xv.z + sv.z * inv;
}

extern "C" void kernel_launch(void* const* d_in, const int* in_sizes, int n_in,
                              void* d_out, int out_size) {
    const float* x_terrain  = (const float*)d_in[0];
    const float* polarity   = (const float*)d_in[1];
    const float* x_torus    = (const float*)d_in[2];
    const int*   seq_ei     = (const int*)d_in[3];
    const int*   assign_src = (const int*)d_in[4];
    const int*   assign_dst = (const int*)d_in[5];
    const int*   tr_ei      = (const int*)d_in[6];
    const float* W_seq      = (const float*)d_in[7];
    const float* op_W       = (const float*)d_in[8];
    const float* op_b       = (const float*)d_in[9];
    const float* gate_W     = (const float*)d_in[10];
    const float* gate_b     = (const float*)d_in[11];

    const int TD = 4, OD = 3;
    int n_t   = in_sizes[0] / TD;      // 2,000,000
    int e_as  = in_sizes[4];           // 2,000,000
    int n_tor = in_sizes[2] / OD;      // 1,000,000
    int e_seq = in_sizes[3] / 2;       // 2,000,000
    int e_tr  = in_sizes[6] / 2;       // 8,000,000
    int n_ops = in_sizes[9] / TD;      // 4

    float* out_t   = (float*)d_out;            // [n_t, 4]
    float* out_tor = out_t + (size_t)n_t * TD; // [n_tor, 3]

    const int B = 256;
    k_init<<<(n_t + B - 1) / B, B>>>((const float4*)x_terrain, (float4*)out_t,
                                     x_torus, gate_W, gate_b, n_t, n_tor);

    int t_seq = (e_seq + 1) / 2;
    k_edges_a<<<(t_seq + B - 1) / B, B>>>(seq_ei, seq_ei + e_seq, assign_src,
                                          (const float4*)x_terrain, W_seq,
                                          (float4*)out_t, e_seq);

    k_op<<<(n_t + B - 1) / B, B>>>((float4*)out_t, assign_dst, polarity,
                                   op_W, op_b, n_t, e_as, n_ops);

    int t_tr = (e_tr + 3) / 4;
    k_transport<<<(t_tr + B - 1) / B, B>>>(tr_ei, tr_ei + e_tr, gate_W, e_tr);

    k_finalize<<<(n_tor + B - 1) / B, B>>>(out_tor, n_tor);
}

// round 3
// speedup vs baseline: 1.1715x; 1.0724x over previous
#include <cuda_runtime.h>

// Scratch (problem-sized per spec):
//   g_sum   : per-torus-node accumulator {sum_x, sum_y, sum_z, count}
//   g_stage : per-torus-node {x, y, z, precomputed_dst_gate_term}
//   g_first : per-terrain-node first assignment edge (segment_min)
__device__ float4 g_sum[1000000];
__device__ float4 g_stage[1000000];
__device__ int    g_first[2000000];

#define HX_INT_MAX 0x7fffffff

// ---------------------------------------------------------------------------
// Terrain chain, kernel T1: copy x_terrain -> out (residual base), g_first=MAX
// ---------------------------------------------------------------------------
__global__ void k_init_terrain(const float4* __restrict__ x_terrain4,
                               float4* __restrict__ out_t4, int n_t) {
    int i = blockIdx.x * blockDim.x + threadIdx.x;
    if (i >= n_t) return;
    out_t4[i] = x_terrain4[i];
    g_first[i] = HX_INT_MAX;
}

// ---------------------------------------------------------------------------
// Torus chain, kernel K1: g_sum = 0; g_stage[n] = {x_tor[n], a_n},
// a_n = gate_W[0:3]·x_tor[n] + gate_b
// ---------------------------------------------------------------------------
__global__ void k_init_torus(const float* __restrict__ x_tor,
                             const float* __restrict__ gate_W,
                             const float* __restrict__ gate_b,
                             int n_tor) {
    int i = blockIdx.x * blockDim.x + threadIdx.x;
    if (i >= n_tor) return;
    g_sum[i] = make_float4(0.f, 0.f, 0.f, 0.f);
    float x0 = x_tor[3 * i + 0];
    float x1 = x_tor[3 * i + 1];
    float x2 = x_tor[3 * i + 2];
    float a = __ldg(&gate_W[0]) * x0 + __ldg(&gate_W[1]) * x1
            + __ldg(&gate_W[2]) * x2 + __ldg(&gate_b[0]);
    g_stage[i] = make_float4(x0, x1, x2, a);
}

// ---------------------------------------------------------------------------
// Terrain chain, kernel T2: fused seq-conv scatter + assignment segment-min.
// 2 edges per thread (int2 index loads).
// ---------------------------------------------------------------------------
__global__ void k_edges_a(const int* __restrict__ seq_src,
                          const int* __restrict__ seq_dst,
                          const int* __restrict__ assign_src,
                          const float4* __restrict__ x_terrain4,
                          const float* __restrict__ W_seq,
                          float4* __restrict__ out_t4,
                          int e_seq) {
    int t = blockIdx.x * blockDim.x + threadIdx.x;
    int e0 = 2 * t;
    if (e0 >= e_seq) return;

    float w[16];
#pragma unroll
    for (int j = 0; j < 16; ++j) w[j] = __ldg(&W_seq[j]);

    int n = (e0 + 1 < e_seq) ? 2 : 1;
    int2 s2, d2, a2;
    if (n == 2) {
        s2 = __ldg((const int2*)(seq_src) + t);
        d2 = __ldg((const int2*)(seq_dst) + t);
        a2 = __ldg((const int2*)(assign_src) + t);
    } else {
        s2.x = seq_src[e0]; d2.x = seq_dst[e0]; a2.x = assign_src[e0];
        s2.y = 0; d2.y = 0; a2.y = 0;
    }

#pragma unroll
    for (int k = 0; k < 2; ++k) {
        if (k >= n) break;
        int s = (k == 0) ? s2.x : s2.y;
        int d = (k == 0) ? d2.x : d2.y;
        int a = (k == 0) ? a2.x : a2.y;
        atomicMin(&g_first[a], e0 + k);
        float4 x = __ldg(&x_terrain4[s]);
        float m0 = w[0]  * x.x + w[1]  * x.y + w[2]  * x.z + w[3]  * x.w;
        float m1 = w[4]  * x.x + w[5]  * x.y + w[6]  * x.z + w[7]  * x.w;
        float m2 = w[8]  * x.x + w[9]  * x.y + w[10] * x.z + w[11] * x.w;
        float m3 = w[12] * x.x + w[13] * x.y + w[14] * x.z + w[15] * x.w;
        float4* dst = &out_t4[d];
        asm volatile("red.global.add.v4.f32 [%0], {%1, %2, %3, %4};"
                     :: "l"(dst), "f"(m0), "f"(m1), "f"(m2), "f"(m3) : "memory");
    }
}

// ---------------------------------------------------------------------------
// Terrain chain, kernel T3: per-node operator transform (in-place).
// ---------------------------------------------------------------------------
__global__ void k_op(float4* __restrict__ out_t4,
                     const int* __restrict__ assign_dst,
                     const float* __restrict__ polarity,
                     const float* __restrict__ op_W,
                     const float* __restrict__ op_b,
                     int n_t, int e_as, int n_ops) {
    int n = blockIdx.x * blockDim.x + threadIdx.x;
    if (n >= n_t) return;
    int f = g_first[n];
    if (f >= e_as) return;

    float4 x = out_t4[n];
    int op = __ldg(&assign_dst[f]);
    op = max(0, min(op, n_ops - 1));
    float p = __ldg(&polarity[f]);

    const float* W = op_W + op * 20;   // [4][5] row-major
    const float* b = op_b + op * 4;

    float4 y;
    y.x = __ldg(&W[0])  * x.x + __ldg(&W[1])  * x.y + __ldg(&W[2])  * x.z + __ldg(&W[3])  * x.w + __ldg(&W[4])  * p + __ldg(&b[0]);
    y.y = __ldg(&W[5])  * x.x + __ldg(&W[6])  * x.y + __ldg(&W[7])  * x.z + __ldg(&W[8])  * x.w + __ldg(&W[9])  * p + __ldg(&b[1]);
    y.z = __ldg(&W[10]) * x.x + __ldg(&W[11]) * x.y + __ldg(&W[12]) * x.z + __ldg(&W[13]) * x.w + __ldg(&W[14]) * p + __ldg(&b[2]);
    y.w = __ldg(&W[15]) * x.x + __ldg(&W[16]) * x.y + __ldg(&W[17]) * x.z + __ldg(&W[18]) * x.w + __ldg(&W[19]) * p + __ldg(&b[3]);
    out_t4[n] = y;
}

// ---------------------------------------------------------------------------
// Torus chain, kernel K2: transport edges, 4 edges/thread (int4 index loads).
// Per edge: LDG.128 stage[src], LDG.32 stage[dst].w, RED.128 g_sum[dst].
// ---------------------------------------------------------------------------
__global__ void k_transport(const int* __restrict__ tr_src,
                            const int* __restrict__ tr_dst,
                            const float* __restrict__ gate_W,
                            int e_tr) {
    int t = blockIdx.x * blockDim.x + threadIdx.x;
    int e0 = 4 * t;
    if (e0 >= e_tr) return;

    float w3 = __ldg(&gate_W[3]);
    float w4 = __ldg(&gate_W[4]);
    float w5 = __ldg(&gate_W[5]);

    const float* stage_f = (const float*)g_stage;

    if (e0 + 3 < e_tr) {
        int4 s4 = __ldg((const int4*)(tr_src) + t);
        int4 d4 = __ldg((const int4*)(tr_dst) + t);
        int ss[4] = {s4.x, s4.y, s4.z, s4.w};
        int dd[4] = {d4.x, d4.y, d4.z, d4.w};
#pragma unroll
        for (int k = 0; k < 4; ++k) {
            float4 v = __ldg(&g_stage[ss[k]]);
            float a  = __ldg(&stage_f[4 * dd[k] + 3]);
            float z  = a + w3 * v.x + w4 * v.y + w5 * v.z;
            float g  = 1.0f / (1.0f + __expf(-z));
            float4* dst = &g_sum[dd[k]];
            asm volatile("red.global.add.v4.f32 [%0], {%1, %2, %3, %4};"
                         :: "l"(dst), "f"(g * v.x), "f"(g * v.y), "f"(g * v.z), "f"(1.0f)
                         : "memory");
        }
    } else {
        for (int e = e0; e < e_tr; ++e) {
            int s = tr_src[e];
            int d = tr_dst[e];
            float4 v = __ldg(&g_stage[s]);
            float a  = __ldg(&stage_f[4 * d + 3]);
            float z  = a + w3 * v.x + w4 * v.y + w5 * v.z;
            float g  = 1.0f / (1.0f + __expf(-z));
            float4* dst = &g_sum[d];
            asm volatile("red.global.add.v4.f32 [%0], {%1, %2, %3, %4};"
                         :: "l"(dst), "f"(g * v.x), "f"(g * v.y), "f"(g * v.z), "f"(1.0f)
                         : "memory");
        }
    }
}

// ---------------------------------------------------------------------------
// Torus chain, kernel K3: finalize. out = x + sum / max(count, 1)
// ---------------------------------------------------------------------------
__global__ void k_finalize(float* __restrict__ out_tor, int n_tor) {
    int n = blockIdx.x * blockDim.x + threadIdx.x;
    if (n >= n_tor) return;
    float4 sv = g_sum[n];
    float4 xv = g_stage[n];
    float inv = 1.0f / fmaxf(sv.w, 1.0f);
    out_tor[3 * n + 0] = xv.x + sv.x * inv;
    out_tor[3 * n + 1] = xv.y + sv.y * inv;
    out_tor[3 * n + 2] = xv.z + sv.z * inv;
}

extern "C" void kernel_launch(void* const* d_in, const int* in_sizes, int n_in,
                              void* d_out, int out_size) {
    const float* x_terrain  = (const float*)d_in[0];
    const float* polarity   = (const float*)d_in[1];
    const float* x_torus    = (const float*)d_in[2];
    const int*   seq_ei     = (const int*)d_in[3];
    const int*   assign_src = (const int*)d_in[4];
    const int*   assign_dst = (const int*)d_in[5];
    const int*   tr_ei      = (const int*)d_in[6];
    const float* W_seq      = (const float*)d_in[7];
    const float* op_W       = (const float*)d_in[8];
    const float* op_b       = (const float*)d_in[9];
    const float* gate_W     = (const float*)d_in[10];
    const float* gate_b     = (const float*)d_in[11];

    const int TD = 4, OD = 3;
    int n_t   = in_sizes[0] / TD;      // 2,000,000
    int e_as  = in_sizes[4];           // 2,000,000
    int n_tor = in_sizes[2] / OD;      // 1,000,000
    int e_seq = in_sizes[3] / 2;       // 2,000,000
    int e_tr  = in_sizes[6] / 2;       // 8,000,000
    int n_ops = in_sizes[9] / TD;      // 4

    float* out_t   = (float*)d_out;            // [n_t, 4]
    float* out_tor = out_t + (size_t)n_t * TD; // [n_tor, 3]

    // One-time side-stream + events for fork/join graph branches.
    static cudaStream_t s2 = nullptr;
    static cudaEvent_t evFork = nullptr, evJoin = nullptr;
    if (s2 == nullptr) {
        cudaStreamCreateWithFlags(&s2, cudaStreamNonBlocking);
        cudaEventCreateWithFlags(&evFork, cudaEventDisableTiming);
        cudaEventCreateWithFlags(&evJoin, cudaEventDisableTiming);
    }

    const int B = 256;

    // Fork: terrain chain on s2, torus chain on the launch (default) stream.
    cudaEventRecord(evFork, 0);
    cudaStreamWaitEvent(s2, evFork, 0);

    // --- terrain chain (s2) ---
    k_init_terrain<<<(n_t + B - 1) / B, B, 0, s2>>>(
        (const float4*)x_terrain, (float4*)out_t, n_t);

    int t_seq = (e_seq + 1) / 2;
    k_edges_a<<<(t_seq + B - 1) / B, B, 0, s2>>>(
        seq_ei, seq_ei + e_seq, assign_src,
        (const float4*)x_terrain, W_seq, (float4*)out_t, e_seq);

    k_op<<<(n_t + B - 1) / B, B, 0, s2>>>(
        (float4*)out_t, assign_dst, polarity, op_W, op_b, n_t, e_as, n_ops);

    cudaEventRecord(evJoin, s2);

    // --- torus chain (default stream) ---
    k_init_torus<<<(n_tor + B - 1) / B, B>>>(x_torus, gate_W, gate_b, n_tor);

    int t_tr = (e_tr + 3) / 4;
    k_transport<<<(t_tr + B - 1) / B, B>>>(tr_ei, tr_ei + e_tr, gate_W, e_tr);

    k_finalize<<<(n_tor + B - 1) / B, B>>>(out_tor, n_tor);

    // Join terrain branch back into the origin stream.
    cudaStreamWaitEvent(0, evJoin, 0);
}